// round 9
// baseline (speedup 1.0000x reference)
#include <cuda_runtime.h>
#include <cstdint>

// TorchSTFT == elementwise scale (see R1 derivation):
//   out[b,t] = x[b,t] * COLA(t+400) * invnorm, COLA=1.5 in interior.
//
// R7-R9: move the data on the TMA/bulk path instead of LDG/STG. R4/R5/R6 all
// land at 9.0-9.1us with every memory level at ~25% regardless of occupancy,
// MLP, or wave shape. Bulk 16KB chunks: cp.async.bulk gmem->smem, scale in
// smem, cp.async.bulk smem->gmem. 1250 chunks x 16KB == 20.48MB exactly.
// R9 hardening: only thread 0 polls the mbarrier; everyone else waits on
// __syncthreads() (leader-wait pattern; BAR.SYNC cannot deadlock).

#define TIME        160000
#define ROW_F4      (TIME / 4)           // 40000 float4 per row
#define CHUNK_BYTES 16384
#define CHUNK_F4    (CHUNK_BYTES / 16)   // 1024
#define NCHUNKS     1250                 // 1250*16384 B == 32*160000*4 B
#define TPB         128
#define F4_PER_THR  (CHUNK_F4 / TPB)     // 8

// invnorm = sqrt(1 - 0.25 + 1e-8)
#define INVNORM_F 0.86602540956f
// interior gain = 1.5 * invnorm
#define CGAIN_F   1.29903811433f

// Exact partial COLA gain (float); used only on the ~400 edge samples per row.
__device__ __forceinline__ float edge_gain(int t) {
    int p = t + 400;
    int fmin = (p > 799) ? (p - 799 + 199) / 200 : 0;
    int fmax = p / 200;
    if (fmax > 800) fmax = 800;          // F-1 = 800
    float s = 0.0f;
    for (int f = fmin; f <= fmax; ++f) {
        int n = p - 200 * f;             // 0..799
        float w = 0.5f - 0.5f * cospif((float)n * (1.0f / 400.0f));
        s += w * w;
    }
    return s * INVNORM_F;
}

__global__ void __launch_bounds__(TPB)
torchstft_bulk_kernel(const float* __restrict__ in, float* __restrict__ out) {
    __shared__ alignas(128) float4 buf[CHUNK_F4];
    __shared__ alignas(8) uint64_t mbar;

    const uint32_t mbar_a = (uint32_t)__cvta_generic_to_shared(&mbar);
    const uint32_t buf_a  = (uint32_t)__cvta_generic_to_shared(buf);
    const char* src = (const char*)in  + (size_t)blockIdx.x * CHUNK_BYTES;
    char*       dst = (char*)out       + (size_t)blockIdx.x * CHUNK_BYTES;

    if (threadIdx.x == 0) {
        asm volatile("mbarrier.init.shared.b64 [%0], %1;"
                     :: "r"(mbar_a), "r"(1) : "memory");
        // init visible to the async proxy before TMA targets this barrier
        asm volatile("fence.proxy.async.shared::cta;" ::: "memory");
        asm volatile("mbarrier.arrive.expect_tx.shared.b64 _, [%0], %1;"
                     :: "r"(mbar_a), "r"(CHUNK_BYTES) : "memory");
        asm volatile(
            "cp.async.bulk.shared::cta.global.mbarrier::complete_tx::bytes "
            "[%0], [%1], %2, [%3];"
            :: "r"(buf_a), "l"(src), "r"(CHUNK_BYTES), "r"(mbar_a) : "memory");
        // Leader waits for the bulk load (parity phase 0); others use bar.sync.
        asm volatile(
            "{\n\t"
            ".reg .pred P1;\n\t"
            "WAIT_LOOP_%=:\n\t"
            "mbarrier.try_wait.parity.shared.b64 P1, [%0], %1, 0x989680;\n\t"
            "@P1 bra.uni WAIT_DONE_%=;\n\t"
            "bra.uni WAIT_LOOP_%=;\n\t"
            "WAIT_DONE_%=:\n\t"
            "}"
            :: "r"(mbar_a), "r"(0) : "memory");
    }
    __syncthreads();

    // Scale in shared memory.
    const int base_f4 = blockIdx.x * CHUNK_F4;       // global float4 index base
#pragma unroll
    for (int k = 0; k < F4_PER_THR; ++k) {
        int i   = threadIdx.x + k * TPB;             // f4 index within chunk
        int gf4 = base_f4 + i;
        int row = gf4 / ROW_F4;
        int t0  = (gf4 - row * ROW_F4) * 4;          // element offset in row
        float4 v = buf[i];
        if (t0 >= 200 && t0 <= 159796) {             // all 4 in COLA interior
            v.x *= CGAIN_F;
            v.y *= CGAIN_F;
            v.z *= CGAIN_F;
            v.w *= CGAIN_F;
        } else {
            v.x *= edge_gain(t0);
            v.y *= edge_gain(t0 + 1);
            v.z *= edge_gain(t0 + 2);
            v.w *= edge_gain(t0 + 3);
        }
        buf[i] = v;
    }
    __syncthreads();

    // Bulk store smem -> gmem, wait for completion before smem is released.
    if (threadIdx.x == 0) {
        asm volatile("fence.proxy.async.shared::cta;" ::: "memory");
        asm volatile(
            "cp.async.bulk.global.shared::cta.bulk_group [%0], [%1], %2;"
            :: "l"(dst), "r"(buf_a), "r"(CHUNK_BYTES) : "memory");
        asm volatile("cp.async.bulk.commit_group;" ::: "memory");
        asm volatile("cp.async.bulk.wait_group 0;" ::: "memory");
    }
}

extern "C" void kernel_launch(void* const* d_in, const int* in_sizes, int n_in,
                              void* d_out, int out_size) {
    (void)in_sizes; (void)n_in; (void)out_size;
    const float* in = (const float*)d_in[0];
    float* out = (float*)d_out;
    torchstft_bulk_kernel<<<NCHUNKS, TPB>>>(in, out);
}